// round 5
// baseline (speedup 1.0000x reference)
#include <cuda_runtime.h>
#include <cuda_bf16.h>

#define EPS 1e-12f

__device__ __forceinline__ float sel4(float4 q, int r) {
    float v = q.x;
    if (r == 1) v = q.y;
    if (r == 2) v = q.z;
    if (r == 3) v = q.w;
    return v;
}

__global__ __launch_bounds__(256)
void timing_prop_kernel(const float* __restrict__ x_t_arr,
                        const float* __restrict__ x_c_arr,
                        const int*   __restrict__ arc_idxs,
                        const float* __restrict__ vals,
                        const float* __restrict__ t_tbl,
                        const float* __restrict__ c_tbl,
                        const int*   __restrict__ dims,
                        float*       __restrict__ out,
                        int B)
{
    int b = blockIdx.x * blockDim.x + threadIdx.x;
    if (b >= B) return;

    // streamed, never reused -> evict-first
    float x_t = __ldcs(x_t_arr + b);
    float x_c = __ldcs(x_c_arr + b);
    int   a   = __ldcs(arc_idxs + b);

    // dims gather (8B, [N,2] int32) -- keep cached (hot 4MB)
    int2 d = __ldg(reinterpret_cast<const int2*>(dims) + a);
    int td = d.x, cd = d.y;

    // table gathers: two float4 each (rows 32B-aligned) -- keep cached (hot 32MB)
    const float4* tt4 = reinterpret_cast<const float4*>(t_tbl) + 2 * a;
    const float4* ct4 = reinterpret_cast<const float4*>(c_tbl) + 2 * a;
    float4 tA = __ldg(tt4);
    float4 tB = __ldg(tt4 + 1);
    float4 cA = __ldg(ct4);
    float4 cB = __ldg(ct4 + 1);

    float tv[8] = {tA.x, tA.y, tA.z, tA.w, tB.x, tB.y, tB.z, tB.w};
    float cv[8] = {cA.x, cA.y, cA.z, cA.w, cB.x, cB.y, cB.z, cB.w};

    // searchsorted side='right' over the full padded table = count of (tbl <= x)
    int ss_t = 0, ss_c = 0;
    #pragma unroll
    for (int j = 0; j < 8; ++j) {
        ss_t += (tv[j] <= x_t) ? 1 : 0;
        ss_c += (cv[j] <= x_c) ? 1 : 0;
    }

    int max_t = max(td - 1, 0);
    int max_c = max(cd - 1, 0);
    // clamp(min=1) then clamp(max=dim-1), matching reference order
    int t_hi = min(max(ss_t, 1), max_t);
    int c_hi = min(max(ss_c, 1), max_c);
    int t_lo = max(t_hi - 1, 0);
    int c_lo = max(c_hi - 1, 0);

    // register-resident breakpoint selection (SEL chains)
    float t0 = tv[0], t1 = tv[0], c0 = cv[0], c1 = cv[0];
    #pragma unroll
    for (int j = 1; j < 8; ++j) {
        if (t_lo == j) t0 = tv[j];
        if (t_hi == j) t1 = tv[j];
        if (c_lo == j) c0 = cv[j];
        if (c_hi == j) c1 = cv[j];
    }

    float ti = t1 - t0;
    float ci = c1 - c0;
    bool t_deg = fabsf(ti) < EPS;
    bool c_deg = fabsf(ci) < EPS;

    float xt = fminf(fmaxf(x_t, t0), t1);
    float xc = fminf(fmaxf(x_c, c0), c1);

    float ti_s = t_deg ? EPS : ti;
    float ci_s = c_deg ? EPS : ci;

    // degenerate dims collapse these to 0 automatically (xt==t0 after clamp)
    float ft = fminf(fmaxf((xt - t0) / ti_s, 0.0f), 1.0f);
    float fc = fminf(fmaxf((xc - c0) / ci_s, 0.0f), 1.0f);

    // ---- unified branchless corner addressing ----
    //   2D:       i00 = t_lo*cd + c_lo, S=cd, fA=fc, fB=ft
    //   1D-trans: i00 = t_lo,           S=1,  fA=ft, fB=0
    //   1D-cap /
    //   scalar:   i00 = c_lo,           S=1,  fA=fc, fB=0   (fc==0 when cd<=1)
    bool is2d = (td > 1) && (cd > 1);
    bool is1t = (td > 1) && !is2d;
    int i00, S;
    float fA, fB;
    if (is2d)      { i00 = t_lo * cd + c_lo; S = cd; fA = fc; fB = ft; }
    else if (is1t) { i00 = t_lo;             S = 1;  fA = ft; fB = 0.0f; }
    else           { i00 = c_lo;             S = 1;  fA = fc; fB = 0.0f; }

    const float* vrow = vals + (size_t)a * 64;

    // pair (i00, i00+1): one aligned float4 covers both unless i00%4==3 (~25%)
    int base0 = i00 & ~3;
    int r0    = i00 & 3;
    float4 q0 = __ldcs(reinterpret_cast<const float4*>(vrow + base0));
    float v00 = sel4(q0, r0);
    float v01 = sel4(q0, min(r0 + 1, 3));
    if (r0 == 3) v01 = __ldcs(vrow + i00 + 1);

    int i10   = i00 + S;                 // <= 62, +1 <= 63: in-row
    int base1 = i10 & ~3;
    int r1    = i10 & 3;
    float4 q1 = __ldcs(reinterpret_cast<const float4*>(vrow + base1));
    float v10 = sel4(q1, r1);
    float v11 = sel4(q1, min(r1 + 1, 3));
    if (r1 == 3) v11 = __ldcs(vrow + i10 + 1);

    // unified lerp (== reference bilinear / 1D / scalar in every case)
    float rowA = v00 + (v01 - v00) * fA;
    float rowB = v10 + (v11 - v10) * fA;
    float res  = rowA + (rowB - rowA) * fB;

    bool valid = (td > 0) && (cd > 0);
    __stcs(out + b, valid ? res : 0.0f);
}

extern "C" void kernel_launch(void* const* d_in, const int* in_sizes, int n_in,
                              void* d_out, int out_size)
{
    const float* input_trans = (const float*)d_in[0];
    const float* output_caps = (const float*)d_in[1];
    const int*   arc_idxs    = (const int*)d_in[2];
    const float* vals        = (const float*)d_in[3];
    const float* t_tbl       = (const float*)d_in[4];
    const float* c_tbl       = (const float*)d_in[5];
    const int*   dims        = (const int*)d_in[6];
    float*       out         = (float*)d_out;

    int B = in_sizes[0];
    int threads = 256;
    int blocks = (B + threads - 1) / threads;
    timing_prop_kernel<<<blocks, threads>>>(input_trans, output_caps, arc_idxs,
                                            vals, t_tbl, c_tbl, dims, out, B);
}

// round 6
// speedup vs baseline: 1.1221x; 1.1221x over previous
#include <cuda_runtime.h>
#include <cuda_bf16.h>

#define EPS 1e-12f

__global__ __launch_bounds__(256)
void timing_prop_kernel(const float* __restrict__ x_t_arr,
                        const float* __restrict__ x_c_arr,
                        const int*   __restrict__ arc_idxs,
                        const float* __restrict__ vals,
                        const float* __restrict__ t_tbl,
                        const float* __restrict__ c_tbl,
                        const int*   __restrict__ dims,
                        float*       __restrict__ out,
                        int B)
{
    int b = blockIdx.x * blockDim.x + threadIdx.x;
    if (b >= B) return;

    // streamed, zero-reuse -> evict-first so they don't pollute L2
    float x_t = __ldcs(x_t_arr + b);
    float x_c = __ldcs(x_c_arr + b);
    int   a   = __ldcs(arc_idxs + b);

    // dims gather (8B aligned: dims is [N,2] int32) -- hot, keep cached
    int2 d = __ldg(reinterpret_cast<const int2*>(dims) + a);
    int td = d.x, cd = d.y;

    if (td <= 0 || cd <= 0) { __stcs(out + b, 0.0f); return; }

    // table gathers: two float4 each (rows are 8 floats, 32B aligned) -- hot
    const float4* tt4 = reinterpret_cast<const float4*>(t_tbl) + 2 * a;
    const float4* ct4 = reinterpret_cast<const float4*>(c_tbl) + 2 * a;
    float4 tA = __ldg(tt4);
    float4 tB = __ldg(tt4 + 1);
    float4 cA = __ldg(ct4);
    float4 cB = __ldg(ct4 + 1);

    float tv[8] = {tA.x, tA.y, tA.z, tA.w, tB.x, tB.y, tB.z, tB.w};
    float cv[8] = {cA.x, cA.y, cA.z, cA.w, cB.x, cB.y, cB.z, cB.w};

    // searchsorted side='right' over the full padded table = count of (tbl <= x)
    int ss_t = 0, ss_c = 0;
    #pragma unroll
    for (int j = 0; j < 8; ++j) {
        ss_t += (tv[j] <= x_t) ? 1 : 0;
        ss_c += (cv[j] <= x_c) ? 1 : 0;
    }

    int max_t = max(td - 1, 0);
    int max_c = max(cd - 1, 0);
    // clamp(min=1) then clamp(max=dim-1), matching the reference order
    int t_hi = min(max(ss_t, 1), max_t);
    int c_hi = min(max(ss_c, 1), max_c);
    int t_lo = max(t_hi - 1, 0);
    int c_lo = max(c_hi - 1, 0);

    // register-resident selection (SEL chains, no local-memory spill)
    float t0 = tv[0], t1 = tv[0], c0 = cv[0], c1 = cv[0];
    #pragma unroll
    for (int j = 1; j < 8; ++j) {
        if (t_lo == j) t0 = tv[j];
        if (t_hi == j) t1 = tv[j];
        if (c_lo == j) c0 = cv[j];
        if (c_hi == j) c1 = cv[j];
    }

    float ti = t1 - t0;
    float ci = c1 - c0;
    bool t_deg = fabsf(ti) < EPS;
    bool c_deg = fabsf(ci) < EPS;

    float xt = fminf(fmaxf(x_t, t0), t1);
    float xc = fminf(fmaxf(x_c, c0), c1);

    float ti_s = t_deg ? EPS : ti;
    float ci_s = c_deg ? EPS : ci;

    float ft = fminf(fmaxf((xt - t0) / ti_s, 0.0f), 1.0f);
    float fc = fminf(fmaxf((xc - c0) / ci_s, 0.0f), 1.0f);

    const float* vrow = vals + (size_t)a * 64;
    float res;

    if (td > 1 && cd > 1) {
        // 2D bilinear — row-major with ACTUAL cap-dim stride cd
        int i00 = t_lo * cd + c_lo;
        int i01 = t_lo * cd + c_hi;
        int i10 = t_hi * cd + c_lo;
        int i11 = t_hi * cd + c_hi;
        float v00 = __ldg(vrow + i00);
        float v01 = __ldg(vrow + i01);
        float v10 = __ldg(vrow + i10);
        float v11 = __ldg(vrow + i11);
        if (t_deg & c_deg) {
            res = v00;
        } else if (t_deg) {
            res = v00 + (v01 - v00) * fc;
        } else if (c_deg) {
            res = v00 + (v10 - v00) * ft;
        } else {
            float wa = (t1 - xt) * (c1 - xc);
            float wb = (t1 - xt) * (xc - c0);
            float wc = (xt - t0) * (c1 - xc);
            float wd = (xt - t0) * (xc - c0);
            res = (v00 * wa + v01 * wb + v10 * wc + v11 * wd) / (ti_s * ci_s);
        }
    } else if (td > 1) {
        // 1D over trans: values row effectively [T]
        float y0 = __ldg(vrow + t_lo);
        float y1 = __ldg(vrow + t_hi);
        res = t_deg ? y0 : (y0 + (y1 - y0) * ft);
    } else if (cd > 1) {
        // 1D over cap: values row effectively [C]
        float y0 = __ldg(vrow + c_lo);
        float y1 = __ldg(vrow + c_hi);
        res = c_deg ? y0 : (y0 + (y1 - y0) * fc);
    } else {
        res = __ldg(vrow);
    }

    __stcs(out + b, res);
}

extern "C" void kernel_launch(void* const* d_in, const int* in_sizes, int n_in,
                              void* d_out, int out_size)
{
    const float* input_trans = (const float*)d_in[0];
    const float* output_caps = (const float*)d_in[1];
    const int*   arc_idxs    = (const int*)d_in[2];
    const float* vals        = (const float*)d_in[3];
    const float* t_tbl       = (const float*)d_in[4];
    const float* c_tbl       = (const float*)d_in[5];
    const int*   dims        = (const int*)d_in[6];
    float*       out         = (float*)d_out;

    int B = in_sizes[0];
    int threads = 256;
    int blocks = (B + threads - 1) / threads;
    timing_prop_kernel<<<blocks, threads>>>(input_trans, output_caps, arc_idxs,
                                            vals, t_tbl, c_tbl, dims, out, B);
}